// round 12
// baseline (speedup 1.0000x reference)
#include <cuda_runtime.h>
#include <math_constants.h>
#include <cstdint>

#define B 4
#define NH 32
#define HD 128
#define HID 4096
#define S_PAST 8192
#define KV (S_PAST + 1)
#define HEAVY 2048
#define OUTL 16
#define BH (B * NH)

#define RSQRT_HD 0.08838834764831845f   // 1/sqrt(128)
#define RSQRT_OUTL 0.25f                // 1/sqrt(16)
#define FULLMASK 0xffffffffu

// ---------------- scratch (device globals; no allocation) ----------------
__device__ float g_qkv[3 * B * HID];     // pre-rope q,k,v
__device__ float g_q[BH * HD];           // roped q
__device__ float g_knew[BH * HD];        // roped k (appended position)
__device__ float g_vnew[BH * HD];        // v (appended position)
__device__ float g_gq[BH * OUTL];        // quantized gathered q
__device__ float g_attn[BH * KV];        // full attention logits
__device__ float g_gattn[BH * KV];       // label (quantized) logits
__device__ float g_kth[BH];
__device__ float g_m[BH];
__device__ float g_invZ[BH];
__device__ float g_hout[B * HID];        // per-head outputs, (b, h*HD+d)

// ---------------- K1: fused QKV GEMV ----------------
__global__ void qkv_gemv_kernel(const float* __restrict__ hid,
                                const float* __restrict__ Wq,
                                const float* __restrict__ Wk,
                                const float* __restrict__ Wv) {
    int t = blockIdx.x;
    int which = t >> 12;           // HID = 4096 = 2^12
    int row = t & (HID - 1);
    const float* W = (which == 0) ? Wq : (which == 1) ? Wk : Wv;
    const float4* w4 = reinterpret_cast<const float4*>(W + (size_t)row * HID);
    const float4* h4 = reinterpret_cast<const float4*>(hid);

    float a0 = 0.f, a1 = 0.f, a2 = 0.f, a3 = 0.f;
    for (int i = threadIdx.x; i < HID / 4; i += blockDim.x) {
        float4 w = w4[i];
        float4 h;
        h = h4[i];
        a0 += w.x * h.x + w.y * h.y + w.z * h.z + w.w * h.w;
        h = h4[i + (HID / 4)];
        a1 += w.x * h.x + w.y * h.y + w.z * h.z + w.w * h.w;
        h = h4[i + 2 * (HID / 4)];
        a2 += w.x * h.x + w.y * h.y + w.z * h.z + w.w * h.w;
        h = h4[i + 3 * (HID / 4)];
        a3 += w.x * h.x + w.y * h.y + w.z * h.z + w.w * h.w;
    }
#pragma unroll
    for (int o = 16; o; o >>= 1) {
        a0 += __shfl_down_sync(FULLMASK, a0, o);
        a1 += __shfl_down_sync(FULLMASK, a1, o);
        a2 += __shfl_down_sync(FULLMASK, a2, o);
        a3 += __shfl_down_sync(FULLMASK, a3, o);
    }
    __shared__ float s[4][4];
    int warp = threadIdx.x >> 5, lane = threadIdx.x & 31;
    if (lane == 0) { s[warp][0] = a0; s[warp][1] = a1; s[warp][2] = a2; s[warp][3] = a3; }
    __syncthreads();
    if (threadIdx.x < 4) {
        float sum = s[0][threadIdx.x] + s[1][threadIdx.x] + s[2][threadIdx.x] + s[3][threadIdx.x];
        g_qkv[((size_t)which * B + threadIdx.x) * HID + row] = sum;
    }
}

// ---------------- K2: RoPE + gq quantization + zero g_hout ----------------
__global__ void rope_kernel(const float* __restrict__ cosp,
                            const float* __restrict__ sinp,
                            const int* __restrict__ schan) {
    int bh = blockIdx.x;
    int b = bh >> 5, h = bh & 31;
    int d = threadIdx.x;

    g_hout[bh * HD + d] = 0.f;   // zero accumulator for K5 atomics

    float q = g_qkv[(0 * B + b) * HID + h * HD + d];
    float k = g_qkv[(1 * B + b) * HID + h * HD + d];
    float v = g_qkv[(2 * B + b) * HID + h * HD + d];
    float c = cosp[b * HD + d];
    float sn = sinp[b * HD + d];

    __shared__ float sq[HD], sk[HD], sqr[HD];
    sq[d] = q; sk[d] = k;
    __syncthreads();
    float rq = (d < HD / 2) ? -sq[d + HD / 2] : sq[d - HD / 2];
    float rk = (d < HD / 2) ? -sk[d + HD / 2] : sk[d - HD / 2];
    float qr = q * c + rq * sn;
    float kr = k * c + rk * sn;
    g_q[bh * HD + d] = qr;
    g_knew[bh * HD + d] = kr;
    g_vnew[bh * HD + d] = v;
    sqr[d] = qr;
    __syncthreads();

    if (d < 32) {
        float val = 0.f;
        if (d < OUTL) val = sqr[schan[h * HD + d]];
        float mn = (d < OUTL) ? val : CUDART_INF_F;
        float mx = (d < OUTL) ? val : -CUDART_INF_F;
#pragma unroll
        for (int o = 16; o; o >>= 1) {
            mn = fminf(mn, __shfl_xor_sync(FULLMASK, mn, o));
            mx = fmaxf(mx, __shfl_xor_sync(FULLMASK, mx, o));
        }
        float range = mx - mn;
        if (range == 0.f) range = 1.f;
        float scale = 15.f / range;
        float qq = fminf(fmaxf(rintf((val - mn) * scale), 0.f), 15.f);
        float deq = qq / scale + mn;
        if (d < OUTL) g_gq[bh * OUTL + d] = deq;
    }
}

// ---------------- K3: attn + gattn, low-instruction reductions ----------------
// 4 rows/warp. Dot: xor16 + half-merge -> 12 shfl for 4 rows.
// gattn: 8-lane group per row, 2 channels/lane -> 9 shfl for 4 rows.
__global__ void attn_kernel(const float* __restrict__ pk,
                            const int* __restrict__ schan, int bh0) {
    __shared__ float sq[HD];
    __shared__ float sgq[OUTL];
    __shared__ int sch[OUTL];
    int bh = bh0 + blockIdx.y;
    int h = bh & 31;
    int tid = threadIdx.x;
    if (tid < HD) sq[tid] = g_q[bh * HD + tid];
    else if (tid < HD + OUTL) sgq[tid - HD] = g_gq[bh * OUTL + (tid - HD)];
    else if (tid < HD + 2 * OUTL) sch[tid - HD - OUTL] = schan[h * HD + (tid - HD - OUTL)];
    __syncthreads();

    int warp = tid >> 5, lane = tid & 31;
    int group = lane >> 3;             // 0..3 : which of the 4 rows this lane's
    int il = lane & 7;                 //        gattn work belongs to
    float4 q4 = reinterpret_cast<const float4*>(sq)[lane];
    int c0 = sch[2 * il], c1 = sch[2 * il + 1];
    float gq0 = sgq[2 * il], gq1 = sgq[2 * il + 1];

    int j0 = blockIdx.x * 32 + warp;   // rows j0, j0+8, j0+16, j0+24

    // ---- batched row loads: maximize MLP ----
    const float* krow[4];
    float4 k4[4];
#pragma unroll
    for (int r = 0; r < 4; r++) {
        int j = j0 + r * 8;
        int jc = (j < KV) ? j : KV - 1;
        krow[r] = (jc < S_PAST) ? pk + ((size_t)bh * S_PAST + jc) * HD
                                : g_knew + (size_t)bh * HD;
    }
#pragma unroll
    for (int r = 0; r < 4; r++)
        k4[r] = __ldg(&reinterpret_cast<const float4*>(krow[r])[lane]);

    // gathers: 2 channels of this lane's group-row (L1 hits)
    const float* myrow = krow[group];
    float gk0 = __ldg(&myrow[c0]);
    float gk1 = __ldg(&myrow[c1]);

    // ---- dot partials ----
    float dot[4];
#pragma unroll
    for (int r = 0; r < 4; r++)
        dot[r] = fmaf(k4[r].x, q4.x, fmaf(k4[r].y, q4.y,
                 fmaf(k4[r].z, q4.z, k4[r].w * q4.w)));

    // ---- dot reduce: one xor16 round, then merge halves ----
#pragma unroll
    for (int r = 0; r < 4; r++)
        dot[r] += __shfl_xor_sync(FULLMASK, dot[r], 16);
    float x = (lane < 16) ? dot[0] : dot[1];
    float y = (lane < 16) ? dot[2] : dot[3];
#pragma unroll
    for (int o = 8; o; o >>= 1) {
        x += __shfl_xor_sync(FULLMASK, x, o);
        y += __shfl_xor_sync(FULLMASK, y, o);
    }
    // lanes 0..15: x = dot(row j0),   y = dot(row j0+16)
    // lanes 16..31: x = dot(row j0+8), y = dot(row j0+24)

    // ---- gattn: min/max/p within each 8-lane group (3 rounds each) ----
    float mn = fminf(gk0, gk1);
    float mx = fmaxf(gk0, gk1);
#pragma unroll
    for (int o = 4; o; o >>= 1) {
        mn = fminf(mn, __shfl_xor_sync(FULLMASK, mn, o));
        mx = fmaxf(mx, __shfl_xor_sync(FULLMASK, mx, o));
    }
    float range = mx - mn;
    if (range == 0.f) range = 1.f;
    float scale = 15.f / range;
    float dq0 = fminf(fmaxf(rintf((gk0 - mn) * scale), 0.f), 15.f) / scale + mn;
    float dq1 = fminf(fmaxf(rintf((gk1 - mn) * scale), 0.f), 15.f) / scale + mn;
    float p = fmaf(gq0, dq0, gq1 * dq1);
#pragma unroll
    for (int o = 4; o; o >>= 1)
        p += __shfl_xor_sync(FULLMASK, p, o);

    // ---- stores ----
    if (il == 0) {                       // lanes 0,8,16,24: one gattn row each
        int j = j0 + group * 8;
        if (j < KV) g_gattn[(size_t)bh * KV + j] = p * RSQRT_OUTL;
    }
    if (lane == 0) {
        if (j0 < KV)      g_attn[(size_t)bh * KV + j0]      = x * RSQRT_HD;
        if (j0 + 16 < KV) g_attn[(size_t)bh * KV + j0 + 16] = y * RSQRT_HD;
    } else if (lane == 16) {
        if (j0 + 8 < KV)  g_attn[(size_t)bh * KV + j0 + 8]  = x * RSQRT_HD;
        if (j0 + 24 < KV) g_attn[(size_t)bh * KV + j0 + 24] = y * RSQRT_HD;
    }
}

// ---------------- K4: radix-select + softmax stats (512 thr, measured) ----
#define ST 512                 // threads
#define NC 8                   // privatized hist copies (2 warps/copy)
__global__ void select_kernel() {
    __shared__ unsigned int skey[KV];        // 32772 B
    __shared__ unsigned int hist[NC][256];   // 8192 B
    __shared__ float sred[ST / 32 + 1];
    __shared__ unsigned int s_prefix, s_k;

    int bh = blockIdx.x;
    int tid = threadIdx.x;
    int warp = tid >> 5, lane = tid & 31;
    int copy = warp >> 1;

    for (int j = tid; j < KV; j += ST) {
        unsigned int u = __float_as_uint(g_gattn[(size_t)bh * KV + j]);
        u = (u & 0x80000000u) ? ~u : (u | 0x80000000u);  // monotonic map
        skey[j] = u;
    }
    if (tid == 0) { s_prefix = 0u; s_k = HEAVY; }
    __syncthreads();

#pragma unroll
    for (int pass = 0; pass < 4; pass++) {
        int shift = 24 - 8 * pass;
        for (int i = tid; i < NC * 256; i += ST) ((unsigned int*)hist)[i] = 0u;
        __syncthreads();
        unsigned int pfx = s_prefix;
        unsigned int k0 = s_k;
        unsigned int pmask = (pass == 0) ? 0u : (0xFFFFFFFFu << (shift + 8));

        for (int base = 0; base < KV; base += ST) {
            int j = base + tid;
            bool inb = (j < KV);
            unsigned int u = inb ? skey[j] : 0u;
            bool active = inb && ((u & pmask) == pfx);
            unsigned int bin = (u >> shift) & 255u;
            unsigned int act = __ballot_sync(FULLMASK, active);
            if (active) {
                unsigned int peers = __match_any_sync(act, bin);
                int leader = __ffs(peers) - 1;
                if (lane == leader)
                    atomicAdd(&hist[copy][bin], __popc(peers));
            }
        }
        __syncthreads();

        // warp 0 alone: reduce copies + suffix-select
        if (warp == 0) {
            unsigned int cnt[8];
            unsigned int tot = 0u;
#pragma unroll
            for (int i = 0; i < 8; i++) {
                unsigned int c = 0u;
#pragma unroll
                for (int cc = 0; cc < NC; cc++) c += hist[cc][lane * 8 + i];
                cnt[i] = c;
                tot += c;
            }
            // inclusive suffix scan over lanes
            unsigned int s = tot;
#pragma unroll
            for (int o = 1; o < 32; o <<= 1) {
                unsigned int v = __shfl_down_sync(FULLMASK, s, o);
                if (lane + o < 32) s += v;
            }
            unsigned int higher = s - tot;       // keys in bins of higher lanes
            if (higher < k0 && higher + tot >= k0) {
                unsigned int run = higher;
#pragma unroll
                for (int i = 7; i >= 0; i--) {
                    run += cnt[i];
                    if (run >= k0) {
                        s_prefix = pfx | ((unsigned int)(lane * 8 + i) << shift);
                        s_k = k0 - (run - cnt[i]);
                        break;
                    }
                }
            }
        }
        __syncthreads();
    }

    unsigned int kkey = s_prefix;
    unsigned int bits = (kkey & 0x80000000u) ? (kkey & 0x7FFFFFFFu) : ~kkey;
    float kth = __uint_as_float(bits);

    // masked max
    float m = -CUDART_INF_F;
    for (int j = tid; j < KV; j += ST)
        if (skey[j] >= kkey) m = fmaxf(m, g_attn[(size_t)bh * KV + j]);
#pragma unroll
    for (int o = 16; o; o >>= 1) m = fmaxf(m, __shfl_xor_sync(FULLMASK, m, o));
    if (lane == 0) sred[warp] = m;
    __syncthreads();
    if (tid < 32) {
        float v = (tid < ST / 32) ? sred[tid] : -CUDART_INF_F;
#pragma unroll
        for (int o = 16; o; o >>= 1) v = fmaxf(v, __shfl_xor_sync(FULLMASK, v, o));
        if (tid == 0) sred[ST / 32] = v;
    }
    __syncthreads();
    m = sred[ST / 32];

    // masked sum of exp
    float z = 0.f;
    for (int j = tid; j < KV; j += ST)
        if (skey[j] >= kkey) z += expf(g_attn[(size_t)bh * KV + j] - m);
#pragma unroll
    for (int o = 16; o; o >>= 1) z += __shfl_xor_sync(FULLMASK, z, o);
    __syncthreads();
    if (lane == 0) sred[warp] = z;
    __syncthreads();
    if (tid == 0) {
        float t = 0.f;
#pragma unroll
        for (int w = 0; w < ST / 32; w++) t += sred[w];
        g_kth[bh] = kth;
        g_m[bh] = m;
        g_invZ[bh] = 1.f / t;
    }
}

// ---------------- K5: selective weighted value accumulation (split 16x) ----
__global__ void outv_kernel(const float* __restrict__ pv) {
    int bh = blockIdx.y;
    int tid = threadIdx.x;
    int warp = tid >> 5, lane = tid & 31;
    float kth = g_kth[bh], m = g_m[bh], invZ = g_invZ[bh];

    float4 acc = make_float4(0.f, 0.f, 0.f, 0.f);
    // 16 blocks x 8 warps = 128 warps stride over KV
    for (int j = blockIdx.x * 8 + warp; j < KV; j += 128) {
        float g = g_gattn[(size_t)bh * KV + j];
        if (g >= kth) {
            float w = expf(g_attn[(size_t)bh * KV + j] - m) * invZ;
            const float* vrow = (j < S_PAST)
                ? pv + ((size_t)bh * S_PAST + j) * HD
                : g_vnew + (size_t)bh * HD;
            float4 v4 = __ldg(&reinterpret_cast<const float4*>(vrow)[lane]);
            acc.x += w * v4.x; acc.y += w * v4.y; acc.z += w * v4.z; acc.w += w * v4.w;
        }
    }
    __shared__ float sacc[8][HD];
    reinterpret_cast<float4*>(&sacc[warp][0])[lane] = acc;
    __syncthreads();
    if (tid < HD) {
        float s = 0.f;
#pragma unroll
        for (int w = 0; w < 8; w++) s += sacc[w][tid];
        atomicAdd(&g_hout[bh * HD + tid], s);
    }
}

// ---------------- K6: output GEMV (hout @ Wo^T) ----------------
__global__ void out_gemv_kernel(const float* __restrict__ Wo,
                                float* __restrict__ out) {
    int row = blockIdx.x;
    const float4* w4 = reinterpret_cast<const float4*>(Wo + (size_t)row * HID);
    const float4* h4 = reinterpret_cast<const float4*>(g_hout);

    float a0 = 0.f, a1 = 0.f, a2 = 0.f, a3 = 0.f;
    for (int i = threadIdx.x; i < HID / 4; i += blockDim.x) {
        float4 w = __ldg(&w4[i]);
        float4 h;
        h = h4[i];
        a0 += w.x * h.x + w.y * h.y + w.z * h.z + w.w * h.w;
        h = h4[i + (HID / 4)];
        a1 += w.x * h.x + w.y * h.y + w.z * h.z + w.w * h.w;
        h = h4[i + 2 * (HID / 4)];
        a2 += w.x * h.x + w.y * h.y + w.z * h.z + w.w * h.w;
        h = h4[i + 3 * (HID / 4)];
        a3 += w.x * h.x + w.y * h.y + w.z * h.z + w.w * h.w;
    }
#pragma unroll
    for (int o = 16; o; o >>= 1) {
        a0 += __shfl_down_sync(FULLMASK, a0, o);
        a1 += __shfl_down_sync(FULLMASK, a1, o);
        a2 += __shfl_down_sync(FULLMASK, a2, o);
        a3 += __shfl_down_sync(FULLMASK, a3, o);
    }
    __shared__ float s[4][4];
    int warp = threadIdx.x >> 5, lane = threadIdx.x & 31;
    if (lane == 0) { s[warp][0] = a0; s[warp][1] = a1; s[warp][2] = a2; s[warp][3] = a3; }
    __syncthreads();
    if (threadIdx.x < 4) {
        float sum = s[0][threadIdx.x] + s[1][threadIdx.x] + s[2][threadIdx.x] + s[3][threadIdx.x];
        out[(size_t)threadIdx.x * HID + row] = sum;
    }
}

// ---------------- launch ----------------
extern "C" void kernel_launch(void* const* d_in, const int* in_sizes, int n_in,
                              void* d_out, int out_size) {
    const float* hid  = (const float*)d_in[0];
    const float* pk   = (const float*)d_in[1];
    const float* pv   = (const float*)d_in[2];
    const float* cosp = (const float*)d_in[3];
    const float* sinp = (const float*)d_in[4];
    const int*   sch  = (const int*)d_in[5];
    const float* Wq   = (const float*)d_in[6];
    const float* Wk   = (const float*)d_in[7];
    const float* Wv   = (const float*)d_in[8];
    const float* Wo   = (const float*)d_in[9];
    float* out = (float*)d_out;

    qkv_gemv_kernel<<<3 * HID, 128>>>(hid, Wq, Wk, Wv);
    rope_kernel<<<BH, 128>>>(cosp, sinp, sch);
    attn_kernel<<<dim3((KV + 31) / 32, BH / 2), 256>>>(pk, sch, 0);
    attn_kernel<<<dim3((KV + 31) / 32, BH / 2), 256>>>(pk, sch, BH / 2);
    select_kernel<<<BH, ST>>>();
    outv_kernel<<<dim3(16, BH), 256>>>(pv);
    out_gemv_kernel<<<HID, 128>>>(Wo, out);
}

// round 13
// speedup vs baseline: 1.4400x; 1.4400x over previous
#include <cuda_runtime.h>
#include <math_constants.h>
#include <cstdint>

#define B 4
#define NH 32
#define HD 128
#define HID 4096
#define S_PAST 8192
#define KV (S_PAST + 1)
#define HEAVY 2048
#define OUTL 16
#define BH (B * NH)

#define RSQRT_HD 0.08838834764831845f   // 1/sqrt(128)
#define RSQRT_OUTL 0.25f                // 1/sqrt(16)
#define INV15 0.06666666666666667f
#define FULLMASK 0xffffffffu
#define TILES 4                          // 32-row tiles per attn block

// ---------------- scratch (device globals; no allocation) ----------------
__device__ float g_qkv[3 * B * HID];     // pre-rope q,k,v
__device__ float g_q[BH * HD];           // roped q
__device__ float g_knew[BH * HD];        // roped k (appended position)
__device__ float g_vnew[BH * HD];        // v (appended position)
__device__ float g_gq[BH * OUTL];        // quantized gathered q
__device__ float g_attn[BH * KV];        // full attention logits
__device__ float g_gattn[BH * KV];       // label (quantized) logits
__device__ float g_kth[BH];
__device__ float g_m[BH];
__device__ float g_invZ[BH];
__device__ float g_hout[B * HID];        // per-head outputs, (b, h*HD+d)

// ---------------- K1: fused QKV GEMV ----------------
__global__ void qkv_gemv_kernel(const float* __restrict__ hid,
                                const float* __restrict__ Wq,
                                const float* __restrict__ Wk,
                                const float* __restrict__ Wv) {
    int t = blockIdx.x;
    int which = t >> 12;           // HID = 4096 = 2^12
    int row = t & (HID - 1);
    const float* W = (which == 0) ? Wq : (which == 1) ? Wk : Wv;
    const float4* w4 = reinterpret_cast<const float4*>(W + (size_t)row * HID);
    const float4* h4 = reinterpret_cast<const float4*>(hid);

    float a0 = 0.f, a1 = 0.f, a2 = 0.f, a3 = 0.f;
    for (int i = threadIdx.x; i < HID / 4; i += blockDim.x) {
        float4 w = w4[i];
        float4 h;
        h = h4[i];
        a0 += w.x * h.x + w.y * h.y + w.z * h.z + w.w * h.w;
        h = h4[i + (HID / 4)];
        a1 += w.x * h.x + w.y * h.y + w.z * h.z + w.w * h.w;
        h = h4[i + 2 * (HID / 4)];
        a2 += w.x * h.x + w.y * h.y + w.z * h.z + w.w * h.w;
        h = h4[i + 3 * (HID / 4)];
        a3 += w.x * h.x + w.y * h.y + w.z * h.z + w.w * h.w;
    }
#pragma unroll
    for (int o = 16; o; o >>= 1) {
        a0 += __shfl_down_sync(FULLMASK, a0, o);
        a1 += __shfl_down_sync(FULLMASK, a1, o);
        a2 += __shfl_down_sync(FULLMASK, a2, o);
        a3 += __shfl_down_sync(FULLMASK, a3, o);
    }
    __shared__ float s[4][4];
    int warp = threadIdx.x >> 5, lane = threadIdx.x & 31;
    if (lane == 0) { s[warp][0] = a0; s[warp][1] = a1; s[warp][2] = a2; s[warp][3] = a3; }
    __syncthreads();
    if (threadIdx.x < 4) {
        float sum = s[0][threadIdx.x] + s[1][threadIdx.x] + s[2][threadIdx.x] + s[3][threadIdx.x];
        g_qkv[((size_t)which * B + threadIdx.x) * HID + row] = sum;
    }
}

// ---------------- K2: RoPE + gq quantization + zero g_hout ----------------
__global__ void rope_kernel(const float* __restrict__ cosp,
                            const float* __restrict__ sinp,
                            const int* __restrict__ schan) {
    int bh = blockIdx.x;
    int b = bh >> 5, h = bh & 31;
    int d = threadIdx.x;

    g_hout[bh * HD + d] = 0.f;   // zero accumulator for K5 atomics

    float q = g_qkv[(0 * B + b) * HID + h * HD + d];
    float k = g_qkv[(1 * B + b) * HID + h * HD + d];
    float v = g_qkv[(2 * B + b) * HID + h * HD + d];
    float c = cosp[b * HD + d];
    float sn = sinp[b * HD + d];

    __shared__ float sq[HD], sk[HD], sqr[HD];
    sq[d] = q; sk[d] = k;
    __syncthreads();
    float rq = (d < HD / 2) ? -sq[d + HD / 2] : sq[d - HD / 2];
    float rk = (d < HD / 2) ? -sk[d + HD / 2] : sk[d - HD / 2];
    float qr = q * c + rq * sn;
    float kr = k * c + rk * sn;
    g_q[bh * HD + d] = qr;
    g_knew[bh * HD + d] = kr;
    g_vnew[bh * HD + d] = v;
    sqr[d] = qr;
    __syncthreads();

    if (d < 32) {
        float val = 0.f;
        if (d < OUTL) val = sqr[schan[h * HD + d]];
        float mn = (d < OUTL) ? val : CUDART_INF_F;
        float mx = (d < OUTL) ? val : -CUDART_INF_F;
#pragma unroll
        for (int o = 16; o; o >>= 1) {
            mn = fminf(mn, __shfl_xor_sync(FULLMASK, mn, o));
            mx = fmaxf(mx, __shfl_xor_sync(FULLMASK, mx, o));
        }
        float range = mx - mn;
        if (range == 0.f) range = 1.f;
        float r15 = range * INV15;
        float scale = __frcp_rn(r15);
        float qq = fminf(fmaxf(rintf((val - mn) * scale), 0.f), 15.f);
        float deq = fmaf(qq, r15, mn);
        if (d < OUTL) g_gq[bh * OUTL + d] = deq;
    }
}

// ---------------- K3: attn + gattn, low-instruction reductions ----------------
// 4 rows/warp, TILES tiles of 32 rows per block (prologue amortized).
// Dot: xor16 + half-merge -> 12 shfl per 4 rows.
// gattn: 8-lane group per row, 2 channels/lane -> 9 shfl per 4 rows.
// Quant: no fp divisions (one RCP per group-tile).
__global__ void attn_kernel(const float* __restrict__ pk,
                            const int* __restrict__ schan) {
    __shared__ float sq[HD];
    __shared__ float sgq[OUTL];
    __shared__ int sch[OUTL];
    int bh = blockIdx.y;
    int h = bh & 31;
    int tid = threadIdx.x;
    if (tid < HD) sq[tid] = g_q[bh * HD + tid];
    else if (tid < HD + OUTL) sgq[tid - HD] = g_gq[bh * OUTL + (tid - HD)];
    else if (tid < HD + 2 * OUTL) sch[tid - HD - OUTL] = schan[h * HD + (tid - HD - OUTL)];
    __syncthreads();

    int warp = tid >> 5, lane = tid & 31;
    int group = lane >> 3;             // 0..3 : which of the 4 rows this lane's
    int il = lane & 7;                 //        gattn work belongs to
    float4 q4 = reinterpret_cast<const float4*>(sq)[lane];
    int c0 = sch[2 * il], c1 = sch[2 * il + 1];
    float gq0 = sgq[2 * il], gq1 = sgq[2 * il + 1];

    const float* kbase = pk + (size_t)bh * S_PAST * HD;
    const float* knew = g_knew + (size_t)bh * HD;
    float* attn_out = g_attn + (size_t)bh * KV;
    float* gattn_out = g_gattn + (size_t)bh * KV;

#pragma unroll
    for (int t = 0; t < TILES; t++) {
        int j0 = (blockIdx.x * TILES + t) * 32 + warp;  // rows j0+8r

        // ---- batched row loads: maximize MLP ----
        const float* krow[4];
        float4 k4[4];
#pragma unroll
        for (int r = 0; r < 4; r++) {
            int j = j0 + r * 8;
            int jc = (j < KV) ? j : KV - 1;
            krow[r] = (jc < S_PAST) ? kbase + (size_t)jc * HD : knew;
        }
#pragma unroll
        for (int r = 0; r < 4; r++)
            k4[r] = __ldg(&reinterpret_cast<const float4*>(krow[r])[lane]);

        // gathers: 2 channels of this lane's group-row (L1 hits)
        const float* myrow = krow[group];
        float gk0 = __ldg(&myrow[c0]);
        float gk1 = __ldg(&myrow[c1]);

        // ---- dot partials ----
        float dot[4];
#pragma unroll
        for (int r = 0; r < 4; r++)
            dot[r] = fmaf(k4[r].x, q4.x, fmaf(k4[r].y, q4.y,
                     fmaf(k4[r].z, q4.z, k4[r].w * q4.w)));

        // ---- dot reduce: one xor16 round, then merge halves ----
#pragma unroll
        for (int r = 0; r < 4; r++)
            dot[r] += __shfl_xor_sync(FULLMASK, dot[r], 16);
        float x = (lane < 16) ? dot[0] : dot[1];
        float y = (lane < 16) ? dot[2] : dot[3];
#pragma unroll
        for (int o = 8; o; o >>= 1) {
            x += __shfl_xor_sync(FULLMASK, x, o);
            y += __shfl_xor_sync(FULLMASK, y, o);
        }
        // lanes 0..15:  x = dot(j0),   y = dot(j0+16)
        // lanes 16..31: x = dot(j0+8), y = dot(j0+24)

        // ---- gattn: min/max/p within each 8-lane group ----
        float mn = fminf(gk0, gk1);
        float mx = fmaxf(gk0, gk1);
#pragma unroll
        for (int o = 4; o; o >>= 1) {
            mn = fminf(mn, __shfl_xor_sync(FULLMASK, mn, o));
            mx = fmaxf(mx, __shfl_xor_sync(FULLMASK, mx, o));
        }
        float range = mx - mn;
        if (range == 0.f) range = 1.f;
        float r15 = range * INV15;          // range/15
        float scale = __frcp_rn(r15);       // ~15/range, no div
        float dq0 = fmaf(fminf(fmaxf(rintf((gk0 - mn) * scale), 0.f), 15.f), r15, mn);
        float dq1 = fmaf(fminf(fmaxf(rintf((gk1 - mn) * scale), 0.f), 15.f), r15, mn);
        float p = fmaf(gq0, dq0, gq1 * dq1);
#pragma unroll
        for (int o = 4; o; o >>= 1)
            p += __shfl_xor_sync(FULLMASK, p, o);

        // ---- stores ----
        if (il == 0) {                     // lanes 0,8,16,24: one gattn row each
            int j = j0 + group * 8;
            if (j < KV) gattn_out[j] = p * RSQRT_OUTL;
        }
        if (lane == 0) {
            if (j0 < KV)      attn_out[j0]      = x * RSQRT_HD;
            if (j0 + 16 < KV) attn_out[j0 + 16] = y * RSQRT_HD;
        } else if (lane == 16) {
            if (j0 + 8 < KV)  attn_out[j0 + 8]  = x * RSQRT_HD;
            if (j0 + 24 < KV) attn_out[j0 + 24] = y * RSQRT_HD;
        }
    }
}

// ---------------- K4: radix-select + softmax stats (512 thr, measured) ----
#define ST 512                 // threads
#define NC 8                   // privatized hist copies (2 warps/copy)
__global__ void select_kernel() {
    __shared__ unsigned int skey[KV];        // 32772 B
    __shared__ unsigned int hist[NC][256];   // 8192 B
    __shared__ float sred[ST / 32 + 1];
    __shared__ unsigned int s_prefix, s_k;

    int bh = blockIdx.x;
    int tid = threadIdx.x;
    int warp = tid >> 5, lane = tid & 31;
    int copy = warp >> 1;

    for (int j = tid; j < KV; j += ST) {
        unsigned int u = __float_as_uint(g_gattn[(size_t)bh * KV + j]);
        u = (u & 0x80000000u) ? ~u : (u | 0x80000000u);  // monotonic map
        skey[j] = u;
    }
    if (tid == 0) { s_prefix = 0u; s_k = HEAVY; }
    __syncthreads();

#pragma unroll
    for (int pass = 0; pass < 4; pass++) {
        int shift = 24 - 8 * pass;
        for (int i = tid; i < NC * 256; i += ST) ((unsigned int*)hist)[i] = 0u;
        __syncthreads();
        unsigned int pfx = s_prefix;
        unsigned int k0 = s_k;
        unsigned int pmask = (pass == 0) ? 0u : (0xFFFFFFFFu << (shift + 8));

        for (int base = 0; base < KV; base += ST) {
            int j = base + tid;
            bool inb = (j < KV);
            unsigned int u = inb ? skey[j] : 0u;
            bool active = inb && ((u & pmask) == pfx);
            unsigned int bin = (u >> shift) & 255u;
            unsigned int act = __ballot_sync(FULLMASK, active);
            if (active) {
                unsigned int peers = __match_any_sync(act, bin);
                int leader = __ffs(peers) - 1;
                if (lane == leader)
                    atomicAdd(&hist[copy][bin], __popc(peers));
            }
        }
        __syncthreads();

        // warp 0 alone: reduce copies + suffix-select
        if (warp == 0) {
            unsigned int cnt[8];
            unsigned int tot = 0u;
#pragma unroll
            for (int i = 0; i < 8; i++) {
                unsigned int c = 0u;
#pragma unroll
                for (int cc = 0; cc < NC; cc++) c += hist[cc][lane * 8 + i];
                cnt[i] = c;
                tot += c;
            }
            // inclusive suffix scan over lanes
            unsigned int s = tot;
#pragma unroll
            for (int o = 1; o < 32; o <<= 1) {
                unsigned int v = __shfl_down_sync(FULLMASK, s, o);
                if (lane + o < 32) s += v;
            }
            unsigned int higher = s - tot;       // keys in bins of higher lanes
            if (higher < k0 && higher + tot >= k0) {
                unsigned int run = higher;
#pragma unroll
                for (int i = 7; i >= 0; i--) {
                    run += cnt[i];
                    if (run >= k0) {
                        s_prefix = pfx | ((unsigned int)(lane * 8 + i) << shift);
                        s_k = k0 - (run - cnt[i]);
                        break;
                    }
                }
            }
        }
        __syncthreads();
    }

    unsigned int kkey = s_prefix;
    unsigned int bits = (kkey & 0x80000000u) ? (kkey & 0x7FFFFFFFu) : ~kkey;
    float kth = __uint_as_float(bits);

    // masked max
    float m = -CUDART_INF_F;
    for (int j = tid; j < KV; j += ST)
        if (skey[j] >= kkey) m = fmaxf(m, g_attn[(size_t)bh * KV + j]);
#pragma unroll
    for (int o = 16; o; o >>= 1) m = fmaxf(m, __shfl_xor_sync(FULLMASK, m, o));
    if (lane == 0) sred[warp] = m;
    __syncthreads();
    if (tid < 32) {
        float v = (tid < ST / 32) ? sred[tid] : -CUDART_INF_F;
#pragma unroll
        for (int o = 16; o; o >>= 1) v = fmaxf(v, __shfl_xor_sync(FULLMASK, v, o));
        if (tid == 0) sred[ST / 32] = v;
    }
    __syncthreads();
    m = sred[ST / 32];

    // masked sum of exp
    float z = 0.f;
    for (int j = tid; j < KV; j += ST)
        if (skey[j] >= kkey) z += expf(g_attn[(size_t)bh * KV + j] - m);
#pragma unroll
    for (int o = 16; o; o >>= 1) z += __shfl_xor_sync(FULLMASK, z, o);
    __syncthreads();
    if (lane == 0) sred[warp] = z;
    __syncthreads();
    if (tid == 0) {
        float t = 0.f;
#pragma unroll
        for (int w = 0; w < ST / 32; w++) t += sred[w];
        g_kth[bh] = kth;
        g_m[bh] = m;
        g_invZ[bh] = 1.f / t;
    }
}

// ---------------- K5: selective weighted value accumulation (split 16x) ----
__global__ void outv_kernel(const float* __restrict__ pv) {
    int bh = blockIdx.y;
    int tid = threadIdx.x;
    int warp = tid >> 5, lane = tid & 31;
    float kth = g_kth[bh], m = g_m[bh], invZ = g_invZ[bh];

    float4 acc = make_float4(0.f, 0.f, 0.f, 0.f);
    // 16 blocks x 8 warps = 128 warps stride over KV
    for (int j = blockIdx.x * 8 + warp; j < KV; j += 128) {
        float g = g_gattn[(size_t)bh * KV + j];
        if (g >= kth) {
            float w = expf(g_attn[(size_t)bh * KV + j] - m) * invZ;
            const float* vrow = (j < S_PAST)
                ? pv + ((size_t)bh * S_PAST + j) * HD
                : g_vnew + (size_t)bh * HD;
            float4 v4 = __ldg(&reinterpret_cast<const float4*>(vrow)[lane]);
            acc.x += w * v4.x; acc.y += w * v4.y; acc.z += w * v4.z; acc.w += w * v4.w;
        }
    }
    __shared__ float sacc[8][HD];
    reinterpret_cast<float4*>(&sacc[warp][0])[lane] = acc;
    __syncthreads();
    if (tid < HD) {
        float s = 0.f;
#pragma unroll
        for (int w = 0; w < 8; w++) s += sacc[w][tid];
        atomicAdd(&g_hout[bh * HD + tid], s);
    }
}

// ---------------- K6: output GEMV (hout @ Wo^T) ----------------
__global__ void out_gemv_kernel(const float* __restrict__ Wo,
                                float* __restrict__ out) {
    int row = blockIdx.x;
    const float4* w4 = reinterpret_cast<const float4*>(Wo + (size_t)row * HID);
    const float4* h4 = reinterpret_cast<const float4*>(g_hout);

    float a0 = 0.f, a1 = 0.f, a2 = 0.f, a3 = 0.f;
    for (int i = threadIdx.x; i < HID / 4; i += blockDim.x) {
        float4 w = __ldg(&w4[i]);
        float4 h;
        h = h4[i];
        a0 += w.x * h.x + w.y * h.y + w.z * h.z + w.w * h.w;
        h = h4[i + (HID / 4)];
        a1 += w.x * h.x + w.y * h.y + w.z * h.z + w.w * h.w;
        h = h4[i + 2 * (HID / 4)];
        a2 += w.x * h.x + w.y * h.y + w.z * h.z + w.w * h.w;
        h = h4[i + 3 * (HID / 4)];
        a3 += w.x * h.x + w.y * h.y + w.z * h.z + w.w * h.w;
    }
#pragma unroll
    for (int o = 16; o; o >>= 1) {
        a0 += __shfl_down_sync(FULLMASK, a0, o);
        a1 += __shfl_down_sync(FULLMASK, a1, o);
        a2 += __shfl_down_sync(FULLMASK, a2, o);
        a3 += __shfl_down_sync(FULLMASK, a3, o);
    }
    __shared__ float s[4][4];
    int warp = threadIdx.x >> 5, lane = threadIdx.x & 31;
    if (lane == 0) { s[warp][0] = a0; s[warp][1] = a1; s[warp][2] = a2; s[warp][3] = a3; }
    __syncthreads();
    if (threadIdx.x < 4) {
        float sum = s[0][threadIdx.x] + s[1][threadIdx.x] + s[2][threadIdx.x] + s[3][threadIdx.x];
        out[(size_t)threadIdx.x * HID + row] = sum;
    }
}

// ---------------- launch ----------------
extern "C" void kernel_launch(void* const* d_in, const int* in_sizes, int n_in,
                              void* d_out, int out_size) {
    const float* hid  = (const float*)d_in[0];
    const float* pk   = (const float*)d_in[1];
    const float* pv   = (const float*)d_in[2];
    const float* cosp = (const float*)d_in[3];
    const float* sinp = (const float*)d_in[4];
    const int*   sch  = (const int*)d_in[5];
    const float* Wq   = (const float*)d_in[6];
    const float* Wk   = (const float*)d_in[7];
    const float* Wv   = (const float*)d_in[8];
    const float* Wo   = (const float*)d_in[9];
    float* out = (float*)d_out;

    qkv_gemv_kernel<<<3 * HID, 128>>>(hid, Wq, Wk, Wv);
    rope_kernel<<<BH, 128>>>(cosp, sinp, sch);
    attn_kernel<<<dim3((KV + 32 * TILES - 1) / (32 * TILES), BH), 256>>>(pk, sch);
    select_kernel<<<BH, ST>>>();
    outv_kernel<<<dim3(16, BH), 256>>>(pv);
    out_gemv_kernel<<<HID, 128>>>(Wo, out);
}

// round 14
// speedup vs baseline: 1.4491x; 1.0063x over previous
#include <cuda_runtime.h>
#include <math_constants.h>
#include <cstdint>

#define B 4
#define NH 32
#define HD 128
#define HID 4096
#define S_PAST 8192
#define KV (S_PAST + 1)
#define HEAVY 2048
#define OUTL 16
#define BH (B * NH)

#define RSQRT_HD 0.08838834764831845f   // 1/sqrt(128)
#define RSQRT_OUTL 0.25f                // 1/sqrt(16)
#define INV15 0.06666666666666667f
#define FULLMASK 0xffffffffu
#define TILES 4                          // 32-row tiles per attn block

// ---------------- scratch (device globals; no allocation) ----------------
__device__ float g_qkv[3 * B * HID];     // pre-rope q,k,v
__device__ float g_q[BH * HD];           // roped q
__device__ float g_knew[BH * HD];        // roped k (appended position)
__device__ float g_vnew[BH * HD];        // v (appended position)
__device__ float g_gq[BH * OUTL];        // quantized gathered q
__device__ float g_attn[BH * KV];        // full attention logits
__device__ float g_gattn[BH * KV];       // label (quantized) logits
__device__ float g_kth[BH];
__device__ float g_m[BH];
__device__ float g_invZ[BH];
__device__ float g_hout[B * HID];        // per-head outputs, (b, h*HD+d)

// ---------------- K1: fused QKV GEMV ----------------
__global__ void qkv_gemv_kernel(const float* __restrict__ hid,
                                const float* __restrict__ Wq,
                                const float* __restrict__ Wk,
                                const float* __restrict__ Wv) {
    int t = blockIdx.x;
    int which = t >> 12;           // HID = 4096 = 2^12
    int row = t & (HID - 1);
    const float* W = (which == 0) ? Wq : (which == 1) ? Wk : Wv;
    const float4* w4 = reinterpret_cast<const float4*>(W + (size_t)row * HID);
    const float4* h4 = reinterpret_cast<const float4*>(hid);

    float a0 = 0.f, a1 = 0.f, a2 = 0.f, a3 = 0.f;
    for (int i = threadIdx.x; i < HID / 4; i += blockDim.x) {
        float4 w = w4[i];
        float4 h;
        h = h4[i];
        a0 += w.x * h.x + w.y * h.y + w.z * h.z + w.w * h.w;
        h = h4[i + (HID / 4)];
        a1 += w.x * h.x + w.y * h.y + w.z * h.z + w.w * h.w;
        h = h4[i + 2 * (HID / 4)];
        a2 += w.x * h.x + w.y * h.y + w.z * h.z + w.w * h.w;
        h = h4[i + 3 * (HID / 4)];
        a3 += w.x * h.x + w.y * h.y + w.z * h.z + w.w * h.w;
    }
#pragma unroll
    for (int o = 16; o; o >>= 1) {
        a0 += __shfl_down_sync(FULLMASK, a0, o);
        a1 += __shfl_down_sync(FULLMASK, a1, o);
        a2 += __shfl_down_sync(FULLMASK, a2, o);
        a3 += __shfl_down_sync(FULLMASK, a3, o);
    }
    __shared__ float s[4][4];
    int warp = threadIdx.x >> 5, lane = threadIdx.x & 31;
    if (lane == 0) { s[warp][0] = a0; s[warp][1] = a1; s[warp][2] = a2; s[warp][3] = a3; }
    __syncthreads();
    if (threadIdx.x < 4) {
        float sum = s[0][threadIdx.x] + s[1][threadIdx.x] + s[2][threadIdx.x] + s[3][threadIdx.x];
        g_qkv[((size_t)which * B + threadIdx.x) * HID + row] = sum;
    }
}

// ---------------- K2: RoPE + gq quantization + zero g_hout ----------------
__global__ void rope_kernel(const float* __restrict__ cosp,
                            const float* __restrict__ sinp,
                            const int* __restrict__ schan) {
    int bh = blockIdx.x;
    int b = bh >> 5, h = bh & 31;
    int d = threadIdx.x;

    g_hout[bh * HD + d] = 0.f;   // zero accumulator for K5 atomics

    float q = g_qkv[(0 * B + b) * HID + h * HD + d];
    float k = g_qkv[(1 * B + b) * HID + h * HD + d];
    float v = g_qkv[(2 * B + b) * HID + h * HD + d];
    float c = cosp[b * HD + d];
    float sn = sinp[b * HD + d];

    __shared__ float sq[HD], sk[HD], sqr[HD];
    sq[d] = q; sk[d] = k;
    __syncthreads();
    float rq = (d < HD / 2) ? -sq[d + HD / 2] : sq[d - HD / 2];
    float rk = (d < HD / 2) ? -sk[d + HD / 2] : sk[d - HD / 2];
    float qr = q * c + rq * sn;
    float kr = k * c + rk * sn;
    g_q[bh * HD + d] = qr;
    g_knew[bh * HD + d] = kr;
    g_vnew[bh * HD + d] = v;
    sqr[d] = qr;
    __syncthreads();

    if (d < 32) {
        float val = 0.f;
        if (d < OUTL) val = sqr[schan[h * HD + d]];
        float mn = (d < OUTL) ? val : CUDART_INF_F;
        float mx = (d < OUTL) ? val : -CUDART_INF_F;
#pragma unroll
        for (int o = 16; o; o >>= 1) {
            mn = fminf(mn, __shfl_xor_sync(FULLMASK, mn, o));
            mx = fmaxf(mx, __shfl_xor_sync(FULLMASK, mx, o));
        }
        float range = mx - mn;
        if (range == 0.f) range = 1.f;
        float scale = 15.f / range;          // exact div: bucket decision matches ref
        float qq = fminf(fmaxf(rintf((val - mn) * scale), 0.f), 15.f);
        float deq = qq / scale + mn;         // fully exact here (cost negligible)
        if (d < OUTL) g_gq[bh * OUTL + d] = deq;
    }
}

// ---------------- K3: attn + gattn, low-instruction reductions ----------------
// 4 rows/warp, TILES tiles of 32 rows per block (prologue amortized).
// Dot: xor16 + half-merge -> 12 shfl per 4 rows.
// gattn: 8-lane group per row, 2 channels/lane -> 9 shfl per 4 rows.
// Quant: ONE exact div for the bucket scale (bit-matches reference rounding);
// fma dequant (1-ulp, ranking-safe).
__global__ void attn_kernel(const float* __restrict__ pk,
                            const int* __restrict__ schan) {
    __shared__ float sq[HD];
    __shared__ float sgq[OUTL];
    __shared__ int sch[OUTL];
    int bh = blockIdx.y;
    int h = bh & 31;
    int tid = threadIdx.x;
    if (tid < HD) sq[tid] = g_q[bh * HD + tid];
    else if (tid < HD + OUTL) sgq[tid - HD] = g_gq[bh * OUTL + (tid - HD)];
    else if (tid < HD + 2 * OUTL) sch[tid - HD - OUTL] = schan[h * HD + (tid - HD - OUTL)];
    __syncthreads();

    int warp = tid >> 5, lane = tid & 31;
    int group = lane >> 3;             // 0..3 : which of the 4 rows this lane's
    int il = lane & 7;                 //        gattn work belongs to
    float4 q4 = reinterpret_cast<const float4*>(sq)[lane];
    int c0 = sch[2 * il], c1 = sch[2 * il + 1];
    float gq0 = sgq[2 * il], gq1 = sgq[2 * il + 1];

    const float* kbase = pk + (size_t)bh * S_PAST * HD;
    const float* knew = g_knew + (size_t)bh * HD;
    float* attn_out = g_attn + (size_t)bh * KV;
    float* gattn_out = g_gattn + (size_t)bh * KV;

#pragma unroll
    for (int t = 0; t < TILES; t++) {
        int j0 = (blockIdx.x * TILES + t) * 32 + warp;  // rows j0+8r

        // ---- batched row loads: maximize MLP ----
        const float* krow[4];
        float4 k4[4];
#pragma unroll
        for (int r = 0; r < 4; r++) {
            int j = j0 + r * 8;
            int jc = (j < KV) ? j : KV - 1;
            krow[r] = (jc < S_PAST) ? kbase + (size_t)jc * HD : knew;
        }
#pragma unroll
        for (int r = 0; r < 4; r++)
            k4[r] = __ldg(&reinterpret_cast<const float4*>(krow[r])[lane]);

        // gathers: 2 channels of this lane's group-row (L1 hits)
        const float* myrow = krow[group];
        float gk0 = __ldg(&myrow[c0]);
        float gk1 = __ldg(&myrow[c1]);

        // ---- dot partials ----
        float dot[4];
#pragma unroll
        for (int r = 0; r < 4; r++)
            dot[r] = fmaf(k4[r].x, q4.x, fmaf(k4[r].y, q4.y,
                     fmaf(k4[r].z, q4.z, k4[r].w * q4.w)));

        // ---- dot reduce: one xor16 round, then merge halves ----
#pragma unroll
        for (int r = 0; r < 4; r++)
            dot[r] += __shfl_xor_sync(FULLMASK, dot[r], 16);
        float x = (lane < 16) ? dot[0] : dot[1];
        float y = (lane < 16) ? dot[2] : dot[3];
#pragma unroll
        for (int o = 8; o; o >>= 1) {
            x += __shfl_xor_sync(FULLMASK, x, o);
            y += __shfl_xor_sync(FULLMASK, y, o);
        }
        // lanes 0..15:  x = dot(j0),   y = dot(j0+16)
        // lanes 16..31: x = dot(j0+8), y = dot(j0+24)

        // ---- gattn: min/max/p within each 8-lane group ----
        float mn = fminf(gk0, gk1);
        float mx = fmaxf(gk0, gk1);
#pragma unroll
        for (int o = 4; o; o >>= 1) {
            mn = fminf(mn, __shfl_xor_sync(FULLMASK, mn, o));
            mx = fmaxf(mx, __shfl_xor_sync(FULLMASK, mx, o));
        }
        float range = mx - mn;
        if (range == 0.f) range = 1.f;
        float scale = 15.f / range;          // exact div: bucket decision matches ref
        float r15 = range * INV15;           // ~range/15 for cheap dequant
        float dq0 = fmaf(fminf(fmaxf(rintf((gk0 - mn) * scale), 0.f), 15.f), r15, mn);
        float dq1 = fmaf(fminf(fmaxf(rintf((gk1 - mn) * scale), 0.f), 15.f), r15, mn);
        float p = fmaf(gq0, dq0, gq1 * dq1);
#pragma unroll
        for (int o = 4; o; o >>= 1)
            p += __shfl_xor_sync(FULLMASK, p, o);

        // ---- stores ----
        if (il == 0) {                     // lanes 0,8,16,24: one gattn row each
            int j = j0 + group * 8;
            if (j < KV) gattn_out[j] = p * RSQRT_OUTL;
        }
        if (lane == 0) {
            if (j0 < KV)      attn_out[j0]      = x * RSQRT_HD;
            if (j0 + 16 < KV) attn_out[j0 + 16] = y * RSQRT_HD;
        } else if (lane == 16) {
            if (j0 + 8 < KV)  attn_out[j0 + 8]  = x * RSQRT_HD;
            if (j0 + 24 < KV) attn_out[j0 + 24] = y * RSQRT_HD;
        }
    }
}

// ---------------- K4: radix-select + softmax stats (512 thr, measured) ----
#define ST 512                 // threads
#define NC 8                   // privatized hist copies (2 warps/copy)
__global__ void select_kernel() {
    __shared__ unsigned int skey[KV];        // 32772 B
    __shared__ unsigned int hist[NC][256];   // 8192 B
    __shared__ float sred[ST / 32 + 1];
    __shared__ unsigned int s_prefix, s_k;

    int bh = blockIdx.x;
    int tid = threadIdx.x;
    int warp = tid >> 5, lane = tid & 31;
    int copy = warp >> 1;

    for (int j = tid; j < KV; j += ST) {
        unsigned int u = __float_as_uint(g_gattn[(size_t)bh * KV + j]);
        u = (u & 0x80000000u) ? ~u : (u | 0x80000000u);  // monotonic map
        skey[j] = u;
    }
    if (tid == 0) { s_prefix = 0u; s_k = HEAVY; }
    __syncthreads();

#pragma unroll
    for (int pass = 0; pass < 4; pass++) {
        int shift = 24 - 8 * pass;
        for (int i = tid; i < NC * 256; i += ST) ((unsigned int*)hist)[i] = 0u;
        __syncthreads();
        unsigned int pfx = s_prefix;
        unsigned int k0 = s_k;
        unsigned int pmask = (pass == 0) ? 0u : (0xFFFFFFFFu << (shift + 8));

        for (int base = 0; base < KV; base += ST) {
            int j = base + tid;
            bool inb = (j < KV);
            unsigned int u = inb ? skey[j] : 0u;
            bool active = inb && ((u & pmask) == pfx);
            unsigned int bin = (u >> shift) & 255u;
            unsigned int act = __ballot_sync(FULLMASK, active);
            if (active) {
                unsigned int peers = __match_any_sync(act, bin);
                int leader = __ffs(peers) - 1;
                if (lane == leader)
                    atomicAdd(&hist[copy][bin], __popc(peers));
            }
        }
        __syncthreads();

        // warp 0 alone: reduce copies + suffix-select
        if (warp == 0) {
            unsigned int cnt[8];
            unsigned int tot = 0u;
#pragma unroll
            for (int i = 0; i < 8; i++) {
                unsigned int c = 0u;
#pragma unroll
                for (int cc = 0; cc < NC; cc++) c += hist[cc][lane * 8 + i];
                cnt[i] = c;
                tot += c;
            }
            // inclusive suffix scan over lanes
            unsigned int s = tot;
#pragma unroll
            for (int o = 1; o < 32; o <<= 1) {
                unsigned int v = __shfl_down_sync(FULLMASK, s, o);
                if (lane + o < 32) s += v;
            }
            unsigned int higher = s - tot;       // keys in bins of higher lanes
            if (higher < k0 && higher + tot >= k0) {
                unsigned int run = higher;
#pragma unroll
                for (int i = 7; i >= 0; i--) {
                    run += cnt[i];
                    if (run >= k0) {
                        s_prefix = pfx | ((unsigned int)(lane * 8 + i) << shift);
                        s_k = k0 - (run - cnt[i]);
                        break;
                    }
                }
            }
        }
        __syncthreads();
    }

    unsigned int kkey = s_prefix;
    unsigned int bits = (kkey & 0x80000000u) ? (kkey & 0x7FFFFFFFu) : ~kkey;
    float kth = __uint_as_float(bits);

    // masked max
    float m = -CUDART_INF_F;
    for (int j = tid; j < KV; j += ST)
        if (skey[j] >= kkey) m = fmaxf(m, g_attn[(size_t)bh * KV + j]);
#pragma unroll
    for (int o = 16; o; o >>= 1) m = fmaxf(m, __shfl_xor_sync(FULLMASK, m, o));
    if (lane == 0) sred[warp] = m;
    __syncthreads();
    if (tid < 32) {
        float v = (tid < ST / 32) ? sred[tid] : -CUDART_INF_F;
#pragma unroll
        for (int o = 16; o; o >>= 1) v = fmaxf(v, __shfl_xor_sync(FULLMASK, v, o));
        if (tid == 0) sred[ST / 32] = v;
    }
    __syncthreads();
    m = sred[ST / 32];

    // masked sum of exp
    float z = 0.f;
    for (int j = tid; j < KV; j += ST)
        if (skey[j] >= kkey) z += expf(g_attn[(size_t)bh * KV + j] - m);
#pragma unroll
    for (int o = 16; o; o >>= 1) z += __shfl_xor_sync(FULLMASK, z, o);
    __syncthreads();
    if (lane == 0) sred[warp] = z;
    __syncthreads();
    if (tid == 0) {
        float t = 0.f;
#pragma unroll
        for (int w = 0; w < ST / 32; w++) t += sred[w];
        g_kth[bh] = kth;
        g_m[bh] = m;
        g_invZ[bh] = 1.f / t;
    }
}

// ---------------- K5: selective weighted value accumulation (split 16x) ----
__global__ void outv_kernel(const float* __restrict__ pv) {
    int bh = blockIdx.y;
    int tid = threadIdx.x;
    int warp = tid >> 5, lane = tid & 31;
    float kth = g_kth[bh], m = g_m[bh], invZ = g_invZ[bh];

    float4 acc = make_float4(0.f, 0.f, 0.f, 0.f);
    // 16 blocks x 8 warps = 128 warps stride over KV
    for (int j = blockIdx.x * 8 + warp; j < KV; j += 128) {
        float g = g_gattn[(size_t)bh * KV + j];
        if (g >= kth) {
            float w = expf(g_attn[(size_t)bh * KV + j] - m) * invZ;
            const float* vrow = (j < S_PAST)
                ? pv + ((size_t)bh * S_PAST + j) * HD
                : g_vnew + (size_t)bh * HD;
            float4 v4 = __ldg(&reinterpret_cast<const float4*>(vrow)[lane]);
            acc.x += w * v4.x; acc.y += w * v4.y; acc.z += w * v4.z; acc.w += w * v4.w;
        }
    }
    __shared__ float sacc[8][HD];
    reinterpret_cast<float4*>(&sacc[warp][0])[lane] = acc;
    __syncthreads();
    if (tid < HD) {
        float s = 0.f;
#pragma unroll
        for (int w = 0; w < 8; w++) s += sacc[w][tid];
        atomicAdd(&g_hout[bh * HD + tid], s);
    }
}

// ---------------- K6: output GEMV (hout @ Wo^T) ----------------
__global__ void out_gemv_kernel(const float* __restrict__ Wo,
                                float* __restrict__ out) {
    int row = blockIdx.x;
    const float4* w4 = reinterpret_cast<const float4*>(Wo + (size_t)row * HID);
    const float4* h4 = reinterpret_cast<const float4*>(g_hout);

    float a0 = 0.f, a1 = 0.f, a2 = 0.f, a3 = 0.f;
    for (int i = threadIdx.x; i < HID / 4; i += blockDim.x) {
        float4 w = __ldg(&w4[i]);
        float4 h;
        h = h4[i];
        a0 += w.x * h.x + w.y * h.y + w.z * h.z + w.w * h.w;
        h = h4[i + (HID / 4)];
        a1 += w.x * h.x + w.y * h.y + w.z * h.z + w.w * h.w;
        h = h4[i + 2 * (HID / 4)];
        a2 += w.x * h.x + w.y * h.y + w.z * h.z + w.w * h.w;
        h = h4[i + 3 * (HID / 4)];
        a3 += w.x * h.x + w.y * h.y + w.z * h.z + w.w * h.w;
    }
#pragma unroll
    for (int o = 16; o; o >>= 1) {
        a0 += __shfl_down_sync(FULLMASK, a0, o);
        a1 += __shfl_down_sync(FULLMASK, a1, o);
        a2 += __shfl_down_sync(FULLMASK, a2, o);
        a3 += __shfl_down_sync(FULLMASK, a3, o);
    }
    __shared__ float s[4][4];
    int warp = threadIdx.x >> 5, lane = threadIdx.x & 31;
    if (lane == 0) { s[warp][0] = a0; s[warp][1] = a1; s[warp][2] = a2; s[warp][3] = a3; }
    __syncthreads();
    if (threadIdx.x < 4) {
        float sum = s[0][threadIdx.x] + s[1][threadIdx.x] + s[2][threadIdx.x] + s[3][threadIdx.x];
        out[(size_t)threadIdx.x * HID + row] = sum;
    }
}

// ---------------- launch ----------------
extern "C" void kernel_launch(void* const* d_in, const int* in_sizes, int n_in,
                              void* d_out, int out_size) {
    const float* hid  = (const float*)d_in[0];
    const float* pk   = (const float*)d_in[1];
    const float* pv   = (const float*)d_in[2];
    const float* cosp = (const float*)d_in[3];
    const float* sinp = (const float*)d_in[4];
    const int*   sch  = (const int*)d_in[5];
    const float* Wq   = (const float*)d_in[6];
    const float* Wk   = (const float*)d_in[7];
    const float* Wv   = (const float*)d_in[8];
    const float* Wo   = (const float*)d_in[9];
    float* out = (float*)d_out;

    qkv_gemv_kernel<<<3 * HID, 128>>>(hid, Wq, Wk, Wv);
    rope_kernel<<<BH, 128>>>(cosp, sinp, sch);
    attn_kernel<<<dim3((KV + 32 * TILES - 1) / (32 * TILES), BH), 256>>>(pk, sch);
    select_kernel<<<BH, ST>>>();
    outv_kernel<<<dim3(16, BH), 256>>>(pv);
    out_gemv_kernel<<<HID, 128>>>(Wo, out);
}

// round 16
// speedup vs baseline: 1.6062x; 1.1084x over previous
#include <cuda_runtime.h>
#include <math_constants.h>
#include <cstdint>

#define B 4
#define NH 32
#define HD 128
#define HID 4096
#define S_PAST 8192
#define KV (S_PAST + 1)
#define HEAVY 2048
#define OUTL 16
#define BH (B * NH)

#define RSQRT_HD 0.08838834764831845f   // 1/sqrt(128)
#define RSQRT_OUTL 0.25f                // 1/sqrt(16)
#define INV15 0.06666666666666667f
#define FULLMASK 0xffffffffu
#define TILES 4                          // 32-row tiles per attn block

// ---------------- scratch (device globals; no allocation) ----------------
__device__ float g_qkv[3 * B * HID];     // pre-rope q,k,v
__device__ float g_q[BH * HD];           // roped q
__device__ float g_knew[BH * HD];        // roped k (appended position)
__device__ float g_vnew[BH * HD];        // v (appended position)
__device__ float g_gq[BH * OUTL];        // quantized gathered q
__device__ float g_attn[BH * KV];        // full attention logits
__device__ float g_gattn[BH * KV];       // label (quantized) logits
__device__ float g_kth[BH];
__device__ float g_m[BH];
__device__ float g_invZ[BH];
__device__ float g_hout[B * HID];        // per-head outputs, (b, h*HD+d)

// ---------------- K1: fused QKV GEMV ----------------
__global__ void qkv_gemv_kernel(const float* __restrict__ hid,
                                const float* __restrict__ Wq,
                                const float* __restrict__ Wk,
                                const float* __restrict__ Wv) {
    int t = blockIdx.x;
    int which = t >> 12;           // HID = 4096 = 2^12
    int row = t & (HID - 1);
    const float* W = (which == 0) ? Wq : (which == 1) ? Wk : Wv;
    const float4* w4 = reinterpret_cast<const float4*>(W + (size_t)row * HID);
    const float4* h4 = reinterpret_cast<const float4*>(hid);

    float a0 = 0.f, a1 = 0.f, a2 = 0.f, a3 = 0.f;
    for (int i = threadIdx.x; i < HID / 4; i += blockDim.x) {
        float4 w = w4[i];
        float4 h;
        h = h4[i];
        a0 += w.x * h.x + w.y * h.y + w.z * h.z + w.w * h.w;
        h = h4[i + (HID / 4)];
        a1 += w.x * h.x + w.y * h.y + w.z * h.z + w.w * h.w;
        h = h4[i + 2 * (HID / 4)];
        a2 += w.x * h.x + w.y * h.y + w.z * h.z + w.w * h.w;
        h = h4[i + 3 * (HID / 4)];
        a3 += w.x * h.x + w.y * h.y + w.z * h.z + w.w * h.w;
    }
#pragma unroll
    for (int o = 16; o; o >>= 1) {
        a0 += __shfl_down_sync(FULLMASK, a0, o);
        a1 += __shfl_down_sync(FULLMASK, a1, o);
        a2 += __shfl_down_sync(FULLMASK, a2, o);
        a3 += __shfl_down_sync(FULLMASK, a3, o);
    }
    __shared__ float s[4][4];
    int warp = threadIdx.x >> 5, lane = threadIdx.x & 31;
    if (lane == 0) { s[warp][0] = a0; s[warp][1] = a1; s[warp][2] = a2; s[warp][3] = a3; }
    __syncthreads();
    if (threadIdx.x < 4) {
        float sum = s[0][threadIdx.x] + s[1][threadIdx.x] + s[2][threadIdx.x] + s[3][threadIdx.x];
        g_qkv[((size_t)which * B + threadIdx.x) * HID + row] = sum;
    }
}

// ---------------- K2: RoPE + gq quantization + zero g_hout ----------------
__global__ void rope_kernel(const float* __restrict__ cosp,
                            const float* __restrict__ sinp,
                            const int* __restrict__ schan) {
    int bh = blockIdx.x;
    int b = bh >> 5, h = bh & 31;
    int d = threadIdx.x;

    g_hout[bh * HD + d] = 0.f;   // zero accumulator for K5 atomics

    float q = g_qkv[(0 * B + b) * HID + h * HD + d];
    float k = g_qkv[(1 * B + b) * HID + h * HD + d];
    float v = g_qkv[(2 * B + b) * HID + h * HD + d];
    float c = cosp[b * HD + d];
    float sn = sinp[b * HD + d];

    __shared__ float sq[HD], sk[HD], sqr[HD];
    sq[d] = q; sk[d] = k;
    __syncthreads();
    float rq = (d < HD / 2) ? -sq[d + HD / 2] : sq[d - HD / 2];
    float rk = (d < HD / 2) ? -sk[d + HD / 2] : sk[d - HD / 2];
    float qr = q * c + rq * sn;
    float kr = k * c + rk * sn;
    g_q[bh * HD + d] = qr;
    g_knew[bh * HD + d] = kr;
    g_vnew[bh * HD + d] = v;
    sqr[d] = qr;
    __syncthreads();

    if (d < 32) {
        float val = 0.f;
        if (d < OUTL) val = sqr[schan[h * HD + d]];
        float mn = (d < OUTL) ? val : CUDART_INF_F;
        float mx = (d < OUTL) ? val : -CUDART_INF_F;
#pragma unroll
        for (int o = 16; o; o >>= 1) {
            mn = fminf(mn, __shfl_xor_sync(FULLMASK, mn, o));
            mx = fmaxf(mx, __shfl_xor_sync(FULLMASK, mx, o));
        }
        float range = mx - mn;
        if (range == 0.f) range = 1.f;
        float scale = 15.f / range;          // exact div: bucket decision matches ref
        float qq = fminf(fmaxf(rintf((val - mn) * scale), 0.f), 15.f);
        float deq = qq / scale + mn;         // fully exact here (cost negligible)
        if (d < OUTL) g_gq[bh * OUTL + d] = deq;
    }
}

// ---------------- K3: attn + gattn, low-instruction reductions ----------------
// 4 rows/warp, TILES tiles of 32 rows per block. Fast path (blocks covering
// only rows < S_PAST): no clamps/selects, one row base pointer per tile,
// constant-offset loads, unconditional stores. Tail block keeps guards.
__global__ void attn_kernel(const float* __restrict__ pk,
                            const int* __restrict__ schan) {
    __shared__ float sq[HD];
    __shared__ float sgq[OUTL];
    __shared__ int sch[OUTL];
    int bh = blockIdx.y;
    int h = bh & 31;
    int tid = threadIdx.x;
    if (tid < HD) sq[tid] = g_q[bh * HD + tid];
    else if (tid < HD + OUTL) sgq[tid - HD] = g_gq[bh * OUTL + (tid - HD)];
    else if (tid < HD + 2 * OUTL) sch[tid - HD - OUTL] = schan[h * HD + (tid - HD - OUTL)];
    __syncthreads();

    int warp = tid >> 5, lane = tid & 31;
    int group = lane >> 3;             // 0..3 : which of the 4 rows this lane's
    int il = lane & 7;                 //        gattn work belongs to
    float4 q4 = reinterpret_cast<const float4*>(sq)[lane];
    int c0 = sch[2 * il], c1 = sch[2 * il + 1];
    float gq0 = sgq[2 * il], gq1 = sgq[2 * il + 1];
    int goff = 8 * group * HD;         // gather-row offset (loop-invariant)

    const float* kbase = pk + (size_t)bh * S_PAST * HD;
    const float* knew = g_knew + (size_t)bh * HD;
    float* attn_out = g_attn + (size_t)bh * KV;
    float* gattn_out = g_gattn + (size_t)bh * KV;

    if (blockIdx.x < S_PAST / (32 * TILES)) {
        // ================= FAST PATH: all rows < S_PAST =================
#pragma unroll
        for (int t = 0; t < TILES; t++) {
            int j0 = (blockIdx.x * TILES + t) * 32 + warp;
            const float* rowp = kbase + (size_t)j0 * HD;

            float4 k4[4];
#pragma unroll
            for (int r = 0; r < 4; r++)
                k4[r] = __ldg(reinterpret_cast<const float4*>(rowp + r * 8 * HD) + lane);
            float gk0 = __ldg(rowp + goff + c0);
            float gk1 = __ldg(rowp + goff + c1);

            float dot[4];
#pragma unroll
            for (int r = 0; r < 4; r++)
                dot[r] = fmaf(k4[r].x, q4.x, fmaf(k4[r].y, q4.y,
                         fmaf(k4[r].z, q4.z, k4[r].w * q4.w)));
#pragma unroll
            for (int r = 0; r < 4; r++)
                dot[r] += __shfl_xor_sync(FULLMASK, dot[r], 16);
            float x = (lane < 16) ? dot[0] : dot[1];
            float y = (lane < 16) ? dot[2] : dot[3];
#pragma unroll
            for (int o = 8; o; o >>= 1) {
                x += __shfl_xor_sync(FULLMASK, x, o);
                y += __shfl_xor_sync(FULLMASK, y, o);
            }

            float mn = fminf(gk0, gk1);
            float mx = fmaxf(gk0, gk1);
#pragma unroll
            for (int o = 4; o; o >>= 1) {
                mn = fminf(mn, __shfl_xor_sync(FULLMASK, mn, o));
                mx = fmaxf(mx, __shfl_xor_sync(FULLMASK, mx, o));
            }
            float range = mx - mn;
            if (range == 0.f) range = 1.f;
            float scale = 15.f / range;      // exact div: bucket matches ref
            float r15 = range * INV15;
            float dq0 = fmaf(fminf(fmaxf(rintf((gk0 - mn) * scale), 0.f), 15.f), r15, mn);
            float dq1 = fmaf(fminf(fmaxf(rintf((gk1 - mn) * scale), 0.f), 15.f), r15, mn);
            float p = fmaf(gq0, dq0, gq1 * dq1);
#pragma unroll
            for (int o = 4; o; o >>= 1)
                p += __shfl_xor_sync(FULLMASK, p, o);

            if (il == 0) gattn_out[j0 + group * 8] = p * RSQRT_OUTL;
            if (lane == 0) {
                attn_out[j0]      = x * RSQRT_HD;
                attn_out[j0 + 16] = y * RSQRT_HD;
            } else if (lane == 16) {
                attn_out[j0 + 8]  = x * RSQRT_HD;
                attn_out[j0 + 24] = y * RSQRT_HD;
            }
        }
    } else {
        // ================= TAIL: guarded (rows >= S_PAST) =================
#pragma unroll
        for (int t = 0; t < TILES; t++) {
            int j0 = (blockIdx.x * TILES + t) * 32 + warp;

            const float* krow[4];
            float4 k4[4];
#pragma unroll
            for (int r = 0; r < 4; r++) {
                int j = j0 + r * 8;
                int jc = (j < KV) ? j : KV - 1;
                krow[r] = (jc < S_PAST) ? kbase + (size_t)jc * HD : knew;
            }
#pragma unroll
            for (int r = 0; r < 4; r++)
                k4[r] = __ldg(&reinterpret_cast<const float4*>(krow[r])[lane]);
            const float* myrow = krow[group];
            float gk0 = __ldg(&myrow[c0]);
            float gk1 = __ldg(&myrow[c1]);

            float dot[4];
#pragma unroll
            for (int r = 0; r < 4; r++)
                dot[r] = fmaf(k4[r].x, q4.x, fmaf(k4[r].y, q4.y,
                         fmaf(k4[r].z, q4.z, k4[r].w * q4.w)));
#pragma unroll
            for (int r = 0; r < 4; r++)
                dot[r] += __shfl_xor_sync(FULLMASK, dot[r], 16);
            float x = (lane < 16) ? dot[0] : dot[1];
            float y = (lane < 16) ? dot[2] : dot[3];
#pragma unroll
            for (int o = 8; o; o >>= 1) {
                x += __shfl_xor_sync(FULLMASK, x, o);
                y += __shfl_xor_sync(FULLMASK, y, o);
            }

            float mn = fminf(gk0, gk1);
            float mx = fmaxf(gk0, gk1);
#pragma unroll
            for (int o = 4; o; o >>= 1) {
                mn = fminf(mn, __shfl_xor_sync(FULLMASK, mn, o));
                mx = fmaxf(mx, __shfl_xor_sync(FULLMASK, mx, o));
            }
            float range = mx - mn;
            if (range == 0.f) range = 1.f;
            float scale = 15.f / range;
            float r15 = range * INV15;
            float dq0 = fmaf(fminf(fmaxf(rintf((gk0 - mn) * scale), 0.f), 15.f), r15, mn);
            float dq1 = fmaf(fminf(fmaxf(rintf((gk1 - mn) * scale), 0.f), 15.f), r15, mn);
            float p = fmaf(gq0, dq0, gq1 * dq1);
#pragma unroll
            for (int o = 4; o; o >>= 1)
                p += __shfl_xor_sync(FULLMASK, p, o);

            if (il == 0) {
                int j = j0 + group * 8;
                if (j < KV) gattn_out[j] = p * RSQRT_OUTL;
            }
            if (lane == 0) {
                if (j0 < KV)      attn_out[j0]      = x * RSQRT_HD;
                if (j0 + 16 < KV) attn_out[j0 + 16] = y * RSQRT_HD;
            } else if (lane == 16) {
                if (j0 + 8 < KV)  attn_out[j0 + 8]  = x * RSQRT_HD;
                if (j0 + 24 < KV) attn_out[j0 + 24] = y * RSQRT_HD;
            }
        }
    }
}

// ---------------- K4: radix-select + softmax stats (register keys) ----------
#define ST 1024                // threads
#define KPT 8                  // keys per thread (8*1024 = 8192; key 8192 on tid 0)
#define NC 16                  // privatized hist copies (2 warps/copy)
__global__ void __launch_bounds__(ST, 1) select_kernel() {
    __shared__ unsigned int hist[NC][256];   // 16384 B
    __shared__ float sred[ST / 32 + 1];
    __shared__ unsigned int s_prefix, s_k;

    int bh = blockIdx.x;
    int tid = threadIdx.x;
    int warp = tid >> 5, lane = tid & 31;
    int copy = warp >> 1;
    const float* gattn = g_gattn + (size_t)bh * KV;
    const float* attn = g_attn + (size_t)bh * KV;

    // keys in registers (coalesced loads, flip once)
    unsigned int u[KPT];
#pragma unroll
    for (int i = 0; i < KPT; i++) {
        unsigned int v = __float_as_uint(gattn[tid + i * ST]);
        u[i] = (v & 0x80000000u) ? ~v : (v | 0x80000000u);
    }
    bool haslast = (tid == 0);
    unsigned int ulast = 0;
    if (haslast) {
        unsigned int v = __float_as_uint(gattn[S_PAST]);
        ulast = (v & 0x80000000u) ? ~v : (v | 0x80000000u);
    }

    if (tid == 0) { s_prefix = 0u; s_k = HEAVY; }
    __syncthreads();

#pragma unroll
    for (int pass = 0; pass < 4; pass++) {
        int shift = 24 - 8 * pass;
        for (int i = tid; i < NC * 256; i += ST) ((unsigned int*)hist)[i] = 0u;
        __syncthreads();
        unsigned int pfx = s_prefix;
        unsigned int k0 = s_k;
        unsigned int pmask = (pass == 0) ? 0u : (0xFFFFFFFFu << (shift + 8));

#pragma unroll
        for (int i = 0; i < KPT; i++) {
            bool active = ((u[i] & pmask) == pfx);
            unsigned int bin = (u[i] >> shift) & 255u;
            unsigned int act = __ballot_sync(FULLMASK, active);
            if (active) {
                unsigned int peers = __match_any_sync(act, bin);
                int leader = __ffs(peers) - 1;
                if (lane == leader)
                    atomicAdd(&hist[copy][bin], __popc(peers));
            }
        }
        if (haslast && ((ulast & pmask) == pfx))
            atomicAdd(&hist[0][(ulast >> shift) & 255u], 1u);
        __syncthreads();

        // warp 0 alone: reduce copies + suffix-select
        if (warp == 0) {
            unsigned int cnt[8];
            unsigned int tot = 0u;
#pragma unroll
            for (int i = 0; i < 8; i++) {
                unsigned int c = 0u;
#pragma unroll
                for (int cc = 0; cc < NC; cc++) c += hist[cc][lane * 8 + i];
                cnt[i] = c;
                tot += c;
            }
            // inclusive suffix scan over lanes
            unsigned int s = tot;
#pragma unroll
            for (int o = 1; o < 32; o <<= 1) {
                unsigned int v = __shfl_down_sync(FULLMASK, s, o);
                if (lane + o < 32) s += v;
            }
            unsigned int higher = s - tot;       // keys in bins of higher lanes
            if (higher < k0 && higher + tot >= k0) {
                unsigned int run = higher;
#pragma unroll
                for (int i = 7; i >= 0; i--) {
                    run += cnt[i];
                    if (run >= k0) {
                        s_prefix = pfx | ((unsigned int)(lane * 8 + i) << shift);
                        s_k = k0 - (run - cnt[i]);
                        break;
                    }
                }
            }
        }
        __syncthreads();
    }

    unsigned int kkey = s_prefix;
    unsigned int bits = (kkey & 0x80000000u) ? (kkey & 0x7FFFFFFFu) : ~kkey;
    float kth = __uint_as_float(bits);

    // masked max
    float m = -CUDART_INF_F;
#pragma unroll
    for (int i = 0; i < KPT; i++)
        if (u[i] >= kkey) m = fmaxf(m, attn[tid + i * ST]);
    if (haslast && ulast >= kkey) m = fmaxf(m, attn[S_PAST]);
#pragma unroll
    for (int o = 16; o; o >>= 1) m = fmaxf(m, __shfl_xor_sync(FULLMASK, m, o));
    if (lane == 0) sred[warp] = m;
    __syncthreads();
    if (tid < 32) {
        float v = sred[tid];
#pragma unroll
        for (int o = 16; o; o >>= 1) v = fmaxf(v, __shfl_xor_sync(FULLMASK, v, o));
        if (tid == 0) sred[ST / 32] = v;
    }
    __syncthreads();
    m = sred[ST / 32];

    // masked sum of exp
    float z = 0.f;
#pragma unroll
    for (int i = 0; i < KPT; i++)
        if (u[i] >= kkey) z += expf(attn[tid + i * ST] - m);
    if (haslast && ulast >= kkey) z += expf(attn[S_PAST] - m);
#pragma unroll
    for (int o = 16; o; o >>= 1) z += __shfl_xor_sync(FULLMASK, z, o);
    __syncthreads();
    if (lane == 0) sred[warp] = z;
    __syncthreads();
    if (tid == 0) {
        float t = 0.f;
#pragma unroll
        for (int w = 0; w < ST / 32; w++) t += sred[w];
        g_kth[bh] = kth;
        g_m[bh] = m;
        g_invZ[bh] = 1.f / t;
    }
}

// ---------------- K5: selective weighted value accumulation (split 16x) ----
__global__ void outv_kernel(const float* __restrict__ pv) {
    int bh = blockIdx.y;
    int tid = threadIdx.x;
    int warp = tid >> 5, lane = tid & 31;
    float kth = g_kth[bh], m = g_m[bh], invZ = g_invZ[bh];

    float4 acc = make_float4(0.f, 0.f, 0.f, 0.f);
    // 16 blocks x 8 warps = 128 warps stride over KV
    for (int j = blockIdx.x * 8 + warp; j < KV; j += 128) {
        float g = g_gattn[(size_t)bh * KV + j];
        if (g >= kth) {
            float w = expf(g_attn[(size_t)bh * KV + j] - m) * invZ;
            const float* vrow = (j < S_PAST)
                ? pv + ((size_t)bh * S_PAST + j) * HD
                : g_vnew + (size_t)bh * HD;
            float4 v4 = __ldg(&reinterpret_cast<const float4*>(vrow)[lane]);
            acc.x += w * v4.x; acc.y += w * v4.y; acc.z += w * v4.z; acc.w += w * v4.w;
        }
    }
    __shared__ float sacc[8][HD];
    reinterpret_cast<float4*>(&sacc[warp][0])[lane] = acc;
    __syncthreads();
    if (tid < HD) {
        float s = 0.f;
#pragma unroll
        for (int w = 0; w < 8; w++) s += sacc[w][tid];
        atomicAdd(&g_hout[bh * HD + tid], s);
    }
}

// ---------------- K6: output GEMV (hout @ Wo^T) ----------------
__global__ void out_gemv_kernel(const float* __restrict__ Wo,
                                float* __restrict__ out) {
    int row = blockIdx.x;
    const float4* w4 = reinterpret_cast<const float4*>(Wo + (size_t)row * HID);
    const float4* h4 = reinterpret_cast<const float4*>(g_hout);

    float a0 = 0.f, a1 = 0.f, a2 = 0.f, a3 = 0.f;
    for (int i = threadIdx.x; i < HID / 4; i += blockDim.x) {
        float4 w = __ldg(&w4[i]);
        float4 h;
        h = h4[i];
        a0 += w.x * h.x + w.y * h.y + w.z * h.z + w.w * h.w;
        h = h4[i + (HID / 4)];
        a1 += w.x * h.x + w.y * h.y + w.z * h.z + w.w * h.w;
        h = h4[i + 2 * (HID / 4)];
        a2 += w.x * h.x + w.y * h.y + w.z * h.z + w.w * h.w;
        h = h4[i + 3 * (HID / 4)];
        a3 += w.x * h.x + w.y * h.y + w.z * h.z + w.w * h.w;
    }
#pragma unroll
    for (int o = 16; o; o >>= 1) {
        a0 += __shfl_down_sync(FULLMASK, a0, o);
        a1 += __shfl_down_sync(FULLMASK, a1, o);
        a2 += __shfl_down_sync(FULLMASK, a2, o);
        a3 += __shfl_down_sync(FULLMASK, a3, o);
    }
    __shared__ float s[4][4];
    int warp = threadIdx.x >> 5, lane = threadIdx.x & 31;
    if (lane == 0) { s[warp][0] = a0; s[warp][1] = a1; s[warp][2] = a2; s[warp][3] = a3; }
    __syncthreads();
    if (threadIdx.x < 4) {
        float sum = s[0][threadIdx.x] + s[1][threadIdx.x] + s[2][threadIdx.x] + s[3][threadIdx.x];
        out[(size_t)threadIdx.x * HID + row] = sum;
    }
}

// ---------------- launch ----------------
extern "C" void kernel_launch(void* const* d_in, const int* in_sizes, int n_in,
                              void* d_out, int out_size) {
    const float* hid  = (const float*)d_in[0];
    const float* pk   = (const float*)d_in[1];
    const float* pv   = (const float*)d_in[2];
    const float* cosp = (const float*)d_in[3];
    const float* sinp = (const float*)d_in[4];
    const int*   sch  = (const int*)d_in[5];
    const float* Wq   = (const float*)d_in[6];
    const float* Wk   = (const float*)d_in[7];
    const float* Wv   = (const float*)d_in[8];
    const float* Wo   = (const float*)d_in[9];
    float* out = (float*)d_out;

    qkv_gemv_kernel<<<3 * HID, 128>>>(hid, Wq, Wk, Wv);
    rope_kernel<<<BH, 128>>>(cosp, sinp, sch);
    attn_kernel<<<dim3((KV + 32 * TILES - 1) / (32 * TILES), BH), 256>>>(pk, sch);
    select_kernel<<<BH, ST>>>();
    outv_kernel<<<dim3(16, BH), 256>>>(pv);
    out_gemv_kernel<<<HID, 128>>>(Wo, out);
}